// round 16
// baseline (speedup 1.0000x reference)
#include <cuda_runtime.h>
#include <cuda_fp16.h>
#include <cstdint>

// ----------------------------------------------------------------------------
// GroupedLinear: out[t,n] = sum_k inp[t,k] * weight[e,n,k],  e = t / 2048
// Base-ISA path (no tcgen05 on plain sm_103 target).
// R15: 98% of the mma.sync accept-rate wall (16 cyc/HMMA/SMSP) at NAT clock.
// R16: persistent CTAs (grid = #SMs). The 2-stage chunk pipeline runs
// CONTINUOUSLY across tile boundaries: chunk 63 issues next tile's chunk 0,
// epilogue STG overlaps its cp.async. Removes 13x (wave transition + cold
// pipeline fill). Fused fp32->fp16 operand path, K=64 chunks, 64x64/warp.
// ----------------------------------------------------------------------------

#define E_EXPERTS 8
#define DIN 4096
#define DOUT 4096
#define T_TOK 16384
#define GROWB (DIN * 4)        // 16384 bytes per fp32 input row

#define CTA_M 256
#define CTA_N 128
#define NCHUNKS 64             // 4096 / 64 K-chunks
#define THREADS 256
#define NTILES ((T_TOK / CTA_M) * (DOUT / CTA_N))   // 2048

#define SROW 288                                // 256B fp32 data + 32B pad
#define A_STAGE_BYTES (CTA_M * SROW)            // 73728
#define B_STAGE_BYTES (CTA_N * SROW)            // 36864
#define STAGE_BYTES (A_STAGE_BYTES + B_STAGE_BYTES)  // 110592
#define SMEM_BYTES (2 * STAGE_BYTES)            // 221184

// ---------------- low-level helpers -----------------------------------------

__device__ __forceinline__ uint32_t smem_to_u32(const void* smem_ptr) {
    uint32_t addr;
    asm("{ .reg .u64 tmp; cvta.to.shared.u64 tmp, %1; cvt.u32.u64 %0, tmp; }"
        : "=r"(addr) : "l"(smem_ptr));
    return addr;
}

__device__ __forceinline__ void cp16(uint32_t s, const void* g) {
    asm volatile("cp.async.cg.shared.global [%0], [%1], 16;"
                 :: "r"(s), "l"(g) : "memory");
}
__device__ __forceinline__ void cp_commit() {
    asm volatile("cp.async.commit_group;" ::: "memory");
}
#define CP_WAIT(n) asm volatile("cp.async.wait_group %0;" :: "n"(n) : "memory")

// Load 2 consecutive fp32 from smem, convert+pack to half2 {lo=k, hi=k+1}.
__device__ __forceinline__ uint32_t lds_cvt(uint32_t addr) {
    float lo, hi;
    asm volatile("ld.shared.v2.f32 {%0,%1}, [%2];"
                 : "=f"(lo), "=f"(hi) : "r"(addr));
    uint32_t r;
    asm("cvt.rn.f16x2.f32 %0, %1, %2;" : "=r"(r) : "f"(hi), "f"(lo));
    return r;
}

__device__ __forceinline__ void mma_16816(float* d, const uint32_t* a,
                                          uint32_t b0, uint32_t b1) {
    asm volatile(
        "mma.sync.aligned.m16n8k16.row.col.f32.f16.f16.f32 "
        "{%0,%1,%2,%3}, {%4,%5,%6,%7}, {%8,%9}, {%0,%1,%2,%3};"
        : "+f"(d[0]), "+f"(d[1]), "+f"(d[2]), "+f"(d[3])
        : "r"(a[0]), "r"(a[1]), "r"(a[2]), "r"(a[3]), "r"(b0), "r"(b1));
}

// Tile decode: N-fastest so concurrent CTAs share A strips + expert B in L2.
__device__ __forceinline__ void tile_bases(int tile, const float* inp,
                                           const float* w,
                                           const char** Ab, const char** Bb) {
    const int n_tile = tile & 31;
    const int m_tile = tile >> 5;
    const int e = m_tile >> 3;
    *Ab = (const char*)(inp + (size_t)(m_tile * CTA_M) * DIN);
    *Bb = (const char*)(w + ((size_t)e * DOUT + (size_t)n_tile * CTA_N) * DIN);
}

// ---------------- GEMM kernel (persistent, fused conversion) -----------------

__global__ void __launch_bounds__(THREADS, 1) gemm_kernel(
    const float* __restrict__ inp, const float* __restrict__ w,
    float* __restrict__ out)
{
    extern __shared__ char smem[];
    const uint32_t smem_u32 = smem_to_u32(smem);
    const int tid = threadIdx.x;
    const int wid = tid >> 5;
    const int lid = tid & 31;

    uint32_t sA[2], sB[2];
#pragma unroll
    for (int s = 0; s < 2; ++s) {
        sA[s] = smem_u32 + s * STAGE_BYTES;
        sB[s] = sA[s] + A_STAGE_BYTES;
    }

    // fp32 chunk = 256B/row. A: 4096 cp (16/thread); B: 2048 cp (8/thread).
#define ISSUE_STAGE(stg, aG, bG) do {                                         \
        _Pragma("unroll")                                                     \
        for (int i_ = 0; i_ < 16; ++i_) {                                     \
            int idx_ = tid + i_ * THREADS;                                    \
            int row_ = idx_ >> 4, seg_ = (idx_ & 15) * 16;                    \
            cp16(sA[stg] + row_ * SROW + seg_,                                \
                 (aG) + (size_t)row_ * GROWB + seg_);                         \
        }                                                                     \
        _Pragma("unroll")                                                     \
        for (int i_ = 0; i_ < 8; ++i_) {                                      \
            int idx_ = tid + i_ * THREADS;                                    \
            int row_ = idx_ >> 4, seg_ = (idx_ & 15) * 16;                    \
            cp16(sB[stg] + row_ * SROW + seg_,                                \
                 (bG) + (size_t)row_ * GROWB + seg_);                         \
        }                                                                     \
    } while (0)

    // Warp layout: 4(M) x 2(N); warp tile 64x64.
    const int wm = wid >> 1;
    const int wn = wid & 1;
    const int fr_row = lid >> 2;
    const int fr_kb  = (lid & 3) * 8;
    const uint32_t aOff = (wm * 64 + fr_row) * SROW + fr_kb;
    const uint32_t bOff = (wn * 64 + fr_row) * SROW + fr_kb;

#define LOAD_A_FRAGS(af, stageA, ksb) do {                                    \
        const uint32_t ab0_ = (stageA) + aOff + (ksb);                        \
        _Pragma("unroll")                                                     \
        for (int mf_ = 0; mf_ < 4; ++mf_) {                                   \
            const uint32_t ab_ = ab0_ + mf_ * (16 * SROW);                    \
            (af)[mf_][0] = lds_cvt(ab_);                                      \
            (af)[mf_][1] = lds_cvt(ab_ + 8 * SROW);                           \
            (af)[mf_][2] = lds_cvt(ab_ + 32);                                 \
            (af)[mf_][3] = lds_cvt(ab_ + 8 * SROW + 32);                      \
        }                                                                     \
    } while (0)
#define LOAD_B_FRAGS(bf, stageB, ksb) do {                                    \
        const uint32_t bb0_ = (stageB) + bOff + (ksb);                        \
        _Pragma("unroll")                                                     \
        for (int nf_ = 0; nf_ < 8; ++nf_) {                                   \
            const uint32_t bb_ = bb0_ + nf_ * (8 * SROW);                     \
            (bf)[nf_][0] = lds_cvt(bb_);                                      \
            (bf)[nf_][1] = lds_cvt(bb_ + 32);                                 \
        }                                                                     \
    } while (0)
#define DO_MMAS(af, bf) do {                                                  \
        _Pragma("unroll")                                                     \
        for (int mf_ = 0; mf_ < 4; ++mf_)                                     \
            _Pragma("unroll")                                                 \
            for (int nf_ = 0; nf_ < 8; ++nf_)                                 \
                mma_16816(acc[mf_][nf_], (af)[mf_], (bf)[nf_][0],             \
                          (bf)[nf_][1]);                                      \
    } while (0)

    float acc[4][8][4];
#pragma unroll
    for (int i = 0; i < 4; ++i)
#pragma unroll
        for (int j = 0; j < 8; ++j)
#pragma unroll
            for (int q = 0; q < 4; ++q) acc[i][j][q] = 0.0f;

    uint32_t af0[4][4], bf0[8][2];   // frags preloaded across barrier (ks0)
    uint32_t af1[4][4], bf1[8][2];   // in-iteration frags

    int tile = blockIdx.x;
    const char *Abase, *Bbase;
    tile_bases(tile, inp, w, &Abase, &Bbase);

    // Prologue: issue (tile, chunk 0); wait; preload its ks0 frags.
    ISSUE_STAGE(0, Abase, Bbase); cp_commit();
    CP_WAIT(0);
    __syncthreads();
    LOAD_A_FRAGS(af0, sA[0], 0);
    LOAD_B_FRAGS(bf0, sB[0], 0);

    int stg = 0;

#pragma unroll 1
    while (true) {
        const int ntile = tile + (int)gridDim.x;
        const bool have_next = (ntile < NTILES);

#pragma unroll 1
        for (int c = 0; c < NCHUNKS; ++c) {
            const int nxt = stg ^ 1;
            // Issue next chunk: (tile, c+1), or next tile's chunk 0.
            if (c + 1 < NCHUNKS) {
                ISSUE_STAGE(nxt, Abase + (size_t)(c + 1) * 256,
                                 Bbase + (size_t)(c + 1) * 256);
            } else if (have_next) {
                const char *nA, *nB;
                tile_bases(ntile, inp, w, &nA, &nB);
                ISSUE_STAGE(nxt, nA, nB);
            }
            cp_commit();

            LOAD_A_FRAGS(af1, sA[stg], 64);
            LOAD_B_FRAGS(bf1, sB[stg], 64);
            DO_MMAS(af0, bf0);             // ks0

            LOAD_A_FRAGS(af0, sA[stg], 128);
            LOAD_B_FRAGS(bf0, sB[stg], 128);
            DO_MMAS(af1, bf1);             // ks1

            LOAD_A_FRAGS(af1, sA[stg], 192);
            LOAD_B_FRAGS(bf1, sB[stg], 192);
            DO_MMAS(af0, bf0);             // ks2

            // Next chunk fully loaded; all lanes done reading buf[stg].
            CP_WAIT(0);
            __syncthreads();

            // Preload next chunk's ks0 (next tile's chunk 0 at c==63; stale
            // discarded data on the very last tile). ks3 covers the latency.
            LOAD_A_FRAGS(af0, sA[nxt], 0);
            LOAD_B_FRAGS(bf0, sB[nxt], 0);
            DO_MMAS(af1, bf1);             // ks3

            stg = nxt;
        }

        // Epilogue for current tile: direct STG from registers.
        {
            const int n_tile = tile & 31;
            const int m_tile = tile >> 5;
            const int row0 = m_tile * CTA_M + wm * 64 + (lid >> 2);
            const int col0 = n_tile * CTA_N + wn * 64 + (lid & 3) * 2;
#pragma unroll
            for (int mf = 0; mf < 4; ++mf) {
#pragma unroll
                for (int nf = 0; nf < 8; ++nf) {
                    float* p0 = out + (size_t)(row0 + mf * 16) * DOUT
                                    + col0 + nf * 8;
                    float* p1 = p0 + 8 * DOUT;
                    *(float2*)p0 = make_float2(acc[mf][nf][0], acc[mf][nf][1]);
                    *(float2*)p1 = make_float2(acc[mf][nf][2], acc[mf][nf][3]);
                    acc[mf][nf][0] = 0.0f; acc[mf][nf][1] = 0.0f;
                    acc[mf][nf][2] = 0.0f; acc[mf][nf][3] = 0.0f;
                }
            }
        }

        if (!have_next) break;
        tile = ntile;
        tile_bases(tile, inp, w, &Abase, &Bbase);
    }
#undef ISSUE_STAGE
#undef LOAD_A_FRAGS
#undef LOAD_B_FRAGS
#undef DO_MMAS
}

// ---------------- launch ------------------------------------------------------

extern "C" void kernel_launch(void* const* d_in, const int* in_sizes, int n_in,
                              void* d_out, int out_size) {
    (void)in_sizes; (void)n_in; (void)out_size;
    const float* inp = (const float*)d_in[0];
    const float* w   = (const float*)d_in[1];
    float* out       = (float*)d_out;

    int dev = 0, nsm = 148;
    cudaGetDevice(&dev);
    cudaDeviceGetAttribute(&nsm, cudaDevAttrMultiProcessorCount, dev);
    if (nsm <= 0 || nsm > NTILES) nsm = 148;

    cudaFuncSetAttribute(gemm_kernel,
                         cudaFuncAttributeMaxDynamicSharedMemorySize,
                         SMEM_BYTES);
    gemm_kernel<<<nsm, THREADS, SMEM_BYTES>>>(inp, w, out);
}

// round 17
// speedup vs baseline: 1.6166x; 1.6166x over previous
#include <cuda_runtime.h>
#include <cuda_fp16.h>
#include <cstdint>

// ----------------------------------------------------------------------------
// GroupedLinear: out[t,n] = sum_k inp[t,k] * weight[e,n,k],  e = t / 2048
// Base-ISA path (no tcgen05 on plain sm_103 target). FINAL (R15 revert):
// - mma.sync accept wall: 16 cyc/HMMA/SMSP, dtype-independent (R13);
//   this kernel sits ~98-99% of it; rolling waves already hide transitions
//   (R16 persistent-CTA experiment regressed 61% via lockstep DRAM bursts).
// - Fused fp32->fp16 operand path: cp.async fp32 tiles, LDS.64 + cvt.f16x2
//   fragment assembly (no scratch, no conversion kernels).
// - K=64 chunks, 2-stage pipeline, cross-barrier ks0 fragment preload.
// - 8 warps, warp tile 64x64, CTA tile 256x128, N-fastest tile order.
// ----------------------------------------------------------------------------

#define E_EXPERTS 8
#define DIN 4096
#define DOUT 4096
#define T_TOK 16384
#define GROWB (DIN * 4)        // 16384 bytes per fp32 input row

#define CTA_M 256
#define CTA_N 128
#define NCHUNKS 64             // 4096 / 64 K-chunks
#define THREADS 256
#define STAGES 2

#define SROW 288                                // 256B fp32 data + 32B pad
#define A_STAGE_BYTES (CTA_M * SROW)            // 73728
#define B_STAGE_BYTES (CTA_N * SROW)            // 36864
#define STAGE_BYTES (A_STAGE_BYTES + B_STAGE_BYTES)  // 110592
#define SMEM_BYTES (STAGES * STAGE_BYTES)       // 221184

// ---------------- low-level helpers -----------------------------------------

__device__ __forceinline__ uint32_t smem_to_u32(const void* smem_ptr) {
    uint32_t addr;
    asm("{ .reg .u64 tmp; cvta.to.shared.u64 tmp, %1; cvt.u32.u64 %0, tmp; }"
        : "=r"(addr) : "l"(smem_ptr));
    return addr;
}

__device__ __forceinline__ void cp16(uint32_t s, const void* g) {
    asm volatile("cp.async.cg.shared.global [%0], [%1], 16;"
                 :: "r"(s), "l"(g) : "memory");
}
__device__ __forceinline__ void cp_commit() {
    asm volatile("cp.async.commit_group;" ::: "memory");
}
#define CP_WAIT(n) asm volatile("cp.async.wait_group %0;" :: "n"(n) : "memory")

// Load 2 consecutive fp32 from smem, convert+pack to half2 {lo=k, hi=k+1}.
__device__ __forceinline__ uint32_t lds_cvt(uint32_t addr) {
    float lo, hi;
    asm volatile("ld.shared.v2.f32 {%0,%1}, [%2];"
                 : "=f"(lo), "=f"(hi) : "r"(addr));
    uint32_t r;
    asm("cvt.rn.f16x2.f32 %0, %1, %2;" : "=r"(r) : "f"(hi), "f"(lo));
    return r;
}

__device__ __forceinline__ void mma_16816(float* d, const uint32_t* a,
                                          uint32_t b0, uint32_t b1) {
    asm volatile(
        "mma.sync.aligned.m16n8k16.row.col.f32.f16.f16.f32 "
        "{%0,%1,%2,%3}, {%4,%5,%6,%7}, {%8,%9}, {%0,%1,%2,%3};"
        : "+f"(d[0]), "+f"(d[1]), "+f"(d[2]), "+f"(d[3])
        : "r"(a[0]), "r"(a[1]), "r"(a[2]), "r"(a[3]), "r"(b0), "r"(b1));
}

// ---------------- GEMM kernel (fused conversion, pipelined frags) ------------

__global__ void __launch_bounds__(THREADS, 1) gemm_kernel(
    const float* __restrict__ inp, const float* __restrict__ w,
    float* __restrict__ out)
{
    extern __shared__ char smem[];
    const uint32_t smem_u32 = smem_to_u32(smem);
    const int tid = threadIdx.x;
    const int wid = tid >> 5;
    const int lid = tid & 31;

    // Tile decode: N-fastest so concurrent CTAs share A strips + expert B in L2
    const int bx = blockIdx.x;
    const int n_tile = bx & 31;           // 32 N-tiles of 128
    const int m_tile = bx >> 5;           // 64 M-tiles of 256
    const int e = m_tile >> 3;            // 2048 tokens / 256 rows = 8 m-tiles

    const char* Abase = (const char*)(inp + (size_t)(m_tile * CTA_M) * DIN);
    const char* Bbase = (const char*)(w + ((size_t)e * DOUT +
                                           (size_t)n_tile * CTA_N) * DIN);

    uint32_t sA[STAGES], sB[STAGES];
#pragma unroll
    for (int s = 0; s < STAGES; ++s) {
        sA[s] = smem_u32 + s * STAGE_BYTES;
        sB[s] = sA[s] + A_STAGE_BYTES;
    }

    // fp32 chunk = 256B per row. A: 256x16 segs = 4096 cp (16/thread);
    // B: 128x16 = 2048 cp (8/thread).
#define ISSUE_STAGE(stg, c) do {                                              \
        const char* aG_ = Abase + (size_t)(c) * 256;                          \
        const char* bG_ = Bbase + (size_t)(c) * 256;                          \
        _Pragma("unroll")                                                     \
        for (int i_ = 0; i_ < 16; ++i_) {                                     \
            int idx_ = tid + i_ * THREADS;                                    \
            int row_ = idx_ >> 4, seg_ = (idx_ & 15) * 16;                    \
            cp16(sA[stg] + row_ * SROW + seg_,                                \
                 aG_ + (size_t)row_ * GROWB + seg_);                          \
        }                                                                     \
        _Pragma("unroll")                                                     \
        for (int i_ = 0; i_ < 8; ++i_) {                                      \
            int idx_ = tid + i_ * THREADS;                                    \
            int row_ = idx_ >> 4, seg_ = (idx_ & 15) * 16;                    \
            cp16(sB[stg] + row_ * SROW + seg_,                                \
                 bG_ + (size_t)row_ * GROWB + seg_);                          \
        }                                                                     \
    } while (0)

    // Warp layout: 4(M) x 2(N); warp tile 64x64.
    const int wm = wid >> 1;
    const int wn = wid & 1;

    // Per-lane fragment base: row (lid>>2), k-offset (lid&3)*2 fp32 = *8 bytes.
    const int fr_row = lid >> 2;
    const int fr_kb  = (lid & 3) * 8;
    const uint32_t aOff = (wm * 64 + fr_row) * SROW + fr_kb;
    const uint32_t bOff = (wn * 64 + fr_row) * SROW + fr_kb;

    // Fragment loaders: ksb = k-step byte offset within 256B row (0,64,128,192)
#define LOAD_A_FRAGS(af, stageA, ksb) do {                                    \
        const uint32_t ab0_ = (stageA) + aOff + (ksb);                        \
        _Pragma("unroll")                                                     \
        for (int mf_ = 0; mf_ < 4; ++mf_) {                                   \
            const uint32_t ab_ = ab0_ + mf_ * (16 * SROW);                    \
            (af)[mf_][0] = lds_cvt(ab_);                                      \
            (af)[mf_][1] = lds_cvt(ab_ + 8 * SROW);                           \
            (af)[mf_][2] = lds_cvt(ab_ + 32);                                 \
            (af)[mf_][3] = lds_cvt(ab_ + 8 * SROW + 32);                      \
        }                                                                     \
    } while (0)
#define LOAD_B_FRAGS(bf, stageB, ksb) do {                                    \
        const uint32_t bb0_ = (stageB) + bOff + (ksb);                        \
        _Pragma("unroll")                                                     \
        for (int nf_ = 0; nf_ < 8; ++nf_) {                                   \
            const uint32_t bb_ = bb0_ + nf_ * (8 * SROW);                     \
            (bf)[nf_][0] = lds_cvt(bb_);                                      \
            (bf)[nf_][1] = lds_cvt(bb_ + 32);                                 \
        }                                                                     \
    } while (0)
#define DO_MMAS(af, bf) do {                                                  \
        _Pragma("unroll")                                                     \
        for (int mf_ = 0; mf_ < 4; ++mf_)                                     \
            _Pragma("unroll")                                                 \
            for (int nf_ = 0; nf_ < 8; ++nf_)                                 \
                mma_16816(acc[mf_][nf_], (af)[mf_], (bf)[nf_][0],             \
                          (bf)[nf_][1]);                                      \
    } while (0)

    float acc[4][8][4];
#pragma unroll
    for (int i = 0; i < 4; ++i)
#pragma unroll
        for (int j = 0; j < 8; ++j)
#pragma unroll
            for (int q = 0; q < 4; ++q) acc[i][j][q] = 0.0f;

    uint32_t af0[4][4], bf0[8][2];   // frags preloaded across barrier (ks0)
    uint32_t af1[4][4], bf1[8][2];   // in-iteration frags (ks1..ks3)

    // Prologue: issue chunk 0; wait; preload its ks0 frags.
    ISSUE_STAGE(0, 0); cp_commit();
    CP_WAIT(0);
    __syncthreads();
    LOAD_A_FRAGS(af0, sA[0], 0);
    LOAD_B_FRAGS(bf0, sB[0], 0);

#pragma unroll 1
    for (int c = 0; c < NCHUNKS; ++c) {
        const int cur = c & 1;
        const int nxt = cur ^ 1;
        // Issue chunk c+1 into the other buffer. Its last readers (chunk c-1,
        // ks1-3 in iter c-1 + ks0 preload in iter c-2) finished before the
        // barrier at the end of iter c-1, which we have passed.
        if (c + 1 < NCHUNKS) ISSUE_STAGE(nxt, c + 1);
        cp_commit();   // unconditional: keeps group counting correct

        // ks1..ks3: load frags then MMA previous ks (frags already in regs).
        LOAD_A_FRAGS(af1, sA[cur], 64);
        LOAD_B_FRAGS(bf1, sB[cur], 64);
        DO_MMAS(af0, bf0);             // ks0

        LOAD_A_FRAGS(af0, sA[cur], 128);
        LOAD_B_FRAGS(bf0, sB[cur], 128);
        DO_MMAS(af1, bf1);             // ks1

        LOAD_A_FRAGS(af1, sA[cur], 192);
        LOAD_B_FRAGS(bf1, sB[cur], 192);
        DO_MMAS(af0, bf0);             // ks2

        // Chunk c+1 loads must be complete and all lanes done reading buf[cur].
        CP_WAIT(0);
        __syncthreads();

        // Preload next chunk's ks0; ks3 MMAs cover the LDS+cvt latency.
        // (On the last iteration this reads stale-but-valid smem; discarded.)
        LOAD_A_FRAGS(af0, sA[nxt], 0);
        LOAD_B_FRAGS(bf0, sB[nxt], 0);
        DO_MMAS(af1, bf1);             // ks3
    }

    // Epilogue: direct STG, float2 per (frag, row-half).
    const int row0 = m_tile * CTA_M + wm * 64 + (lid >> 2);
    const int col0 = n_tile * CTA_N + wn * 64 + (lid & 3) * 2;
#pragma unroll
    for (int mf = 0; mf < 4; ++mf) {
#pragma unroll
        for (int nf = 0; nf < 8; ++nf) {
            float* p0 = out + (size_t)(row0 + mf * 16) * DOUT + col0 + nf * 8;
            float* p1 = p0 + 8 * DOUT;
            *(float2*)p0 = make_float2(acc[mf][nf][0], acc[mf][nf][1]);
            *(float2*)p1 = make_float2(acc[mf][nf][2], acc[mf][nf][3]);
        }
    }
#undef ISSUE_STAGE
#undef LOAD_A_FRAGS
#undef LOAD_B_FRAGS
#undef DO_MMAS
}

// ---------------- launch ------------------------------------------------------

extern "C" void kernel_launch(void* const* d_in, const int* in_sizes, int n_in,
                              void* d_out, int out_size) {
    (void)in_sizes; (void)n_in; (void)out_size;
    const float* inp = (const float*)d_in[0];
    const float* w   = (const float*)d_in[1];
    float* out       = (float*)d_out;

    cudaFuncSetAttribute(gemm_kernel,
                         cudaFuncAttributeMaxDynamicSharedMemorySize,
                         SMEM_BYTES);
    gemm_kernel<<<(T_TOK / CTA_M) * (DOUT / CTA_N), THREADS, SMEM_BYTES>>>(
        inp, w, out);
}